// round 3
// baseline (speedup 1.0000x reference)
#include <cuda_runtime.h>
#include <cstdint>
#include <cstddef>

#define MT 16384            // B*T
#define LSTM_SMEM ((16384 + 8*32*33)*4)

// ------------------------- static device scratch -----------------------------
__device__ float g_h1 [(size_t)MT*1024];
__device__ float g_h2 [(size_t)MT*1024];
__device__ float g_xp [(size_t)MT*4096];
__device__ float g_lo1[(size_t)MT*1024];
__device__ float g_lo2[(size_t)MT*1024];
__device__ float g_hbuf[2*2*512*32];     // [parity][dir][unit][batch]
__device__ unsigned g_barcnt[2];
__device__ unsigned g_bargen[2];

// ------------------------- helpers -------------------------------------------
__device__ __forceinline__ uint32_t f2tf(float x){
  uint32_t r; asm("cvt.rna.tf32.f32 %0, %1;" : "=r"(r) : "f"(x)); return r;
}
__device__ __forceinline__ float fsig(float x){
  return __fdividef(1.f, 1.f + __expf(-x));
}
__device__ __forceinline__ float ftanh(float x){
  return 1.f - __fdividef(2.f, __expf(2.f*x) + 1.f);
}

// ---------------- TF32 GEMM: C[M,N] = A[M,K] * B[N,K]^T (+bias1 +bias2) ------
// BM=128, BN=128, BK=32. 256 threads = 8 warps (2 M x 4 N), warp tile 64x32.
__global__ __launch_bounds__(256) void gemm_tf32(
    const float* __restrict__ A, const float* __restrict__ B,
    const float* __restrict__ bias1, const float* __restrict__ bias2,
    float* __restrict__ C, int M, int N, int K)
{
  __shared__ uint32_t As[32][132];   // k-major, padded
  __shared__ uint32_t Bs[32][132];
  const int tid  = threadIdx.x;
  const int warp = tid >> 5, lane = tid & 31;
  const int gid  = lane >> 2, tig = lane & 3;
  const int wm   = warp & 1,  wn  = warp >> 1;
  const int m0 = blockIdx.x * 128, n0 = blockIdx.y * 128;

  float acc[4][4][4];
  #pragma unroll
  for (int a=0;a<4;a++)
    #pragma unroll
    for (int b=0;b<4;b++)
      #pragma unroll
      for (int c=0;c<4;c++) acc[a][b][c] = 0.f;

  for (int k0 = 0; k0 < K; k0 += 32){
    #pragma unroll
    for (int it = 0; it < 4; ++it){
      int f = tid + it*256;                    // 0..1023
      int row = f >> 3, kq = (f & 7) * 4;
      float4 va = *(const float4*)(A + (size_t)(m0+row)*K + k0 + kq);
      As[kq  ][row] = f2tf(va.x);
      As[kq+1][row] = f2tf(va.y);
      As[kq+2][row] = f2tf(va.z);
      As[kq+3][row] = f2tf(va.w);
      float4 vb = *(const float4*)(B + (size_t)(n0+row)*K + k0 + kq);
      Bs[kq  ][row] = f2tf(vb.x);
      Bs[kq+1][row] = f2tf(vb.y);
      Bs[kq+2][row] = f2tf(vb.z);
      Bs[kq+3][row] = f2tf(vb.w);
    }
    __syncthreads();

    #pragma unroll
    for (int kt = 0; kt < 4; ++kt){
      const int kk = kt*8 + tig;
      uint32_t a[4][4], b[4][2];
      #pragma unroll
      for (int mt = 0; mt < 4; ++mt){
        int r = wm*64 + mt*16 + gid;
        a[mt][0] = As[kk  ][r];   a[mt][1] = As[kk  ][r+8];
        a[mt][2] = As[kk+4][r];   a[mt][3] = As[kk+4][r+8];
      }
      #pragma unroll
      for (int nt = 0; nt < 4; ++nt){
        int cn = wn*32 + nt*8 + gid;
        b[nt][0] = Bs[kk][cn];    b[nt][1] = Bs[kk+4][cn];
      }
      #pragma unroll
      for (int mt = 0; mt < 4; ++mt)
        #pragma unroll
        for (int nt = 0; nt < 4; ++nt)
          asm volatile("mma.sync.aligned.m16n8k8.row.col.f32.tf32.tf32.f32 "
            "{%0,%1,%2,%3}, {%4,%5,%6,%7}, {%8,%9}, {%0,%1,%2,%3};"
            : "+f"(acc[mt][nt][0]), "+f"(acc[mt][nt][1]),
              "+f"(acc[mt][nt][2]), "+f"(acc[mt][nt][3])
            : "r"(a[mt][0]), "r"(a[mt][1]), "r"(a[mt][2]), "r"(a[mt][3]),
              "r"(b[nt][0]), "r"(b[nt][1]));
    }
    __syncthreads();
  }

  #pragma unroll
  for (int mt = 0; mt < 4; ++mt)
    #pragma unroll
    for (int nt = 0; nt < 4; ++nt)
      #pragma unroll
      for (int i = 0; i < 4; ++i){
        int row = m0 + wm*64 + mt*16 + gid + ((i>>1)<<3);
        int col = n0 + wn*32 + nt*8 + tig*2 + (i&1);
        float v = acc[mt][nt][i];
        if (bias1) v += __ldg(bias1 + col);
        if (bias2) v += __ldg(bias2 + col);
        C[(size_t)row*N + col] = v;
      }
}

// ---------------- LayerNorm + LeakyReLU (+ optional length mask) -------------
__global__ __launch_bounds__(256) void ln_lrelu(float* __restrict__ h,
    const float* __restrict__ g, const float* __restrict__ be,
    const int* __restrict__ lens, int use_mask)
{
  __shared__ float sred[8];
  const int row = blockIdx.x, tid = threadIdx.x, lane = tid & 31, w = tid >> 5;
  float* hp = h + (size_t)row*1024;
  float v[4]; float s = 0.f;
  #pragma unroll
  for (int i=0;i<4;i++){ v[i] = hp[tid + i*256]; s += v[i]; }
  #pragma unroll
  for (int o=16;o;o>>=1) s += __shfl_xor_sync(0xffffffffu, s, o);
  if (lane==0) sred[w] = s;
  __syncthreads();
  if (w==0){
    float t2 = (lane < 8) ? sred[lane] : 0.f;
    #pragma unroll
    for (int o=4;o;o>>=1) t2 += __shfl_xor_sync(0xffffffffu, t2, o);
    if (lane==0) sred[0] = t2;
  }
  __syncthreads();
  float mean = sred[0] * (1.f/1024.f);
  __syncthreads();
  float q = 0.f;
  #pragma unroll
  for (int i=0;i<4;i++){ float d = v[i]-mean; q += d*d; }
  #pragma unroll
  for (int o=16;o;o>>=1) q += __shfl_xor_sync(0xffffffffu, q, o);
  if (lane==0) sred[w] = q;
  __syncthreads();
  if (w==0){
    float t2 = (lane < 8) ? sred[lane] : 0.f;
    #pragma unroll
    for (int o=4;o;o>>=1) t2 += __shfl_xor_sync(0xffffffffu, t2, o);
    if (lane==0) sred[0] = t2;
  }
  __syncthreads();
  float rstd = rsqrtf(sred[0]*(1.f/1024.f) + 1e-5f);
  float msk = 1.f;
  if (use_mask){ int b = row >> 9, t = row & 511; msk = (t < lens[b]) ? 1.f : 0.f; }
  #pragma unroll
  for (int i=0;i<4;i++){
    int j = tid + i*256;
    float y = (v[i]-mean)*rstd*g[j] + be[j];
    y = (y >= 0.f) ? y : 0.01f*y;
    hp[j] = y * msk;
  }
}

// ---------------- persistent bidirectional LSTM layer ------------------------
// 128 blocks x 256 threads. dir = blk>>6; each block owns 8 hidden units
// (32 gate-rows). Recurrent weights register-resident (64 floats/thread).
__global__ __launch_bounds__(256) void lstm_kernel(
    const float* __restrict__ xp,     // [16384][4096]: dir0 2048 | dir1 2048
    const float* __restrict__ whh_l,  // [2][2048][512] for this layer
    float* __restrict__ lo)           // [16384][1024]: fwd 512 | bwd 512
{
  extern __shared__ float sm[];
  float* hs   = sm;                   // [512][32]
  float* part = sm + 16384;           // [8][32][33]
  const int tid = threadIdx.x;
  const int dir = blockIdx.x >> 6;
  const int u0  = (blockIdx.x & 63) * 8;
  const int w   = tid >> 5;           // k-chunk (warp)
  const int lr  = tid & 31;           // local gate-row
  const int gate = lr >> 3, jj = lr & 7;
  const int row_g = gate*512 + u0 + jj;

  float wreg[64];
  {
    const float* wr = whh_l + ((size_t)dir*2048 + row_g)*512 + w*64;
    #pragma unroll
    for (int i=0;i<64;i++) wreg[i] = wr[i];
  }

  // cell-update thread mapping: tid = bb*8 + ub
  const int ub = tid & 7;             // unit index j
  const int bb = tid >> 3;            // batch
  float c_reg = 0.f;

  for (int i = tid; i < 16384; i += 256) hs[i] = 0.f;
  __syncthreads();

  const uint32_t hs_base = (uint32_t)__cvta_generic_to_shared(hs);
  volatile unsigned* vgen = (volatile unsigned*)&g_bargen[dir];

  for (int t = 0; t < 512; ++t){
    const int te = dir ? (511 - t) : t;

    // prefetch this step's gate pre-activations for the update thread
    const float* xpp = xp + ((size_t)(bb*512 + te))*4096 + dir*2048 + u0 + ub;
    float xv0 = __ldcs(xpp);
    float xv1 = __ldcs(xpp + 512);
    float xv2 = __ldcs(xpp + 1024);
    float xv3 = __ldcs(xpp + 1536);

    // ---- partial dot: row lr, k in [w*64, w*64+64), all 32 batches --------
    unsigned long long acc[16];
    #pragma unroll
    for (int i=0;i<16;i++) acc[i] = 0ULL;
    uint32_t ha = hs_base + (uint32_t)w*8192;
    #pragma unroll 16
    for (int i=0;i<64;i++){
      unsigned long long w2;
      asm("mov.b64 %0, {%1, %1};" : "=l"(w2) : "f"(wreg[i]));
      #pragma unroll
      for (int q=0;q<8;q++){
        unsigned long long h0,h1;
        asm volatile("ld.shared.v2.u64 {%0,%1}, [%2];"
                     : "=l"(h0), "=l"(h1) : "r"(ha + q*16));
        asm("fma.rn.f32x2 %0, %1, %2, %0;" : "+l"(acc[2*q  ]) : "l"(w2), "l"(h0));
        asm("fma.rn.f32x2 %0, %1, %2, %0;" : "+l"(acc[2*q+1]) : "l"(w2), "l"(h1));
      }
      ha += 128;
    }
    {
      float* pp = part + (w*32 + lr)*33;
      #pragma unroll
      for (int q=0;q<16;q++){
        float lo_, hi_;
        asm("mov.b64 {%0,%1}, %2;" : "=f"(lo_), "=f"(hi_) : "l"(acc[q]));
        pp[2*q] = lo_; pp[2*q+1] = hi_;
      }
    }
    __syncthreads();

    // ---- reduce across 8 k-chunks + cell update (thread = (bb, ub)) -------
    float gsum[4];
    #pragma unroll
    for (int g4=0; g4<4; ++g4){
      int lrow = g4*8 + ub;
      float s = 0.f;
      #pragma unroll
      for (int ww=0; ww<8; ++ww) s += part[(ww*32 + lrow)*33 + bb];
      gsum[g4] = s;
    }
    float ig = fsig (gsum[0] + xv0);
    float fg = fsig (gsum[1] + xv1);
    float gt = ftanh(gsum[2] + xv2);
    float og = fsig (gsum[3] + xv3);
    c_reg = fg*c_reg + ig*gt;
    float hv = og * ftanh(c_reg);

    lo[((size_t)(bb*512 + te))*1024 + dir*512 + u0 + ub] = hv;
    __stcg(g_hbuf + ((t & 1)*2 + dir)*16384 + (u0 + ub)*32 + bb, hv);

    // ---- per-dir grid barrier ---------------------------------------------
    __threadfence();
    __syncthreads();
    if (tid == 0){
      unsigned gen = *vgen;
      unsigned a = atomicAdd(&g_barcnt[dir], 1u);
      if (a == 63u){
        atomicExch(&g_barcnt[dir], 0u);
        __threadfence();
        atomicAdd(&g_bargen[dir], 1u);
      } else {
        while (*vgen == gen) { }
        __threadfence();
      }
    }
    __syncthreads();

    // ---- reload full h(t) into smem ---------------------------------------
    {
      const float4* src = (const float4*)(g_hbuf + ((t&1)*2 + dir)*16384);
      float4* dst = (float4*)hs;
      #pragma unroll
      for (int i=0;i<16;i++) dst[tid + i*256] = __ldcg(src + tid + i*256);
    }
    __syncthreads();
  }
}

// ---------------- attention pooling + classifier head ------------------------
__global__ __launch_bounds__(256) void attn_kernel(
    const float* __restrict__ lo, const float* __restrict__ w_u,
    const float* __restrict__ b_u, const float* __restrict__ Wc,
    const float* __restrict__ bc, const int* __restrict__ lens,
    float* __restrict__ out)
{
  __shared__ float sw[1024];
  __shared__ float sa[512];
  __shared__ float sred[8];
  __shared__ float spool[1024];
  const int b = blockIdx.x, tid = threadIdx.x, lane = tid & 31, w = tid >> 5;
  const int len = lens[b];
  for (int i=tid;i<1024;i+=256) sw[i] = w_u[i];
  __syncthreads();

  for (int t = w; t < 512; t += 8){
    float s = 0.f;
    const float* hp = lo + ((size_t)(b*512+t))*1024;
    #pragma unroll
    for (int i=0;i<32;i++) s += hp[lane + i*32]*sw[lane + i*32];
    #pragma unroll
    for (int o=16;o;o>>=1) s += __shfl_xor_sync(0xffffffffu, s, o);
    if (lane==0) sa[t] = (t < len) ? (s + b_u[0]) : -INFINITY;
  }
  __syncthreads();

  float m = -INFINITY;
  for (int i=tid;i<512;i+=256) m = fmaxf(m, sa[i]);
  #pragma unroll
  for (int o=16;o;o>>=1) m = fmaxf(m, __shfl_xor_sync(0xffffffffu, m, o));
  if (lane==0) sred[w] = m;
  __syncthreads();
  if (w==0){
    float t2 = (lane<8)?sred[lane]:-INFINITY;
    #pragma unroll
    for (int o=4;o;o>>=1) t2 = fmaxf(t2, __shfl_xor_sync(0xffffffffu, t2, o));
    if (lane==0) sred[0] = t2;
  }
  __syncthreads();
  m = sred[0];
  __syncthreads();

  float ssum = 0.f;
  for (int i=tid;i<512;i+=256){ float e = __expf(sa[i]-m); sa[i]=e; ssum += e; }
  #pragma unroll
  for (int o=16;o;o>>=1) ssum += __shfl_xor_sync(0xffffffffu, ssum, o);
  if (lane==0) sred[w] = ssum;
  __syncthreads();
  if (w==0){
    float t2 = (lane<8)?sred[lane]:0.f;
    #pragma unroll
    for (int o=4;o;o>>=1) t2 += __shfl_xor_sync(0xffffffffu, t2, o);
    if (lane==0) sred[0] = t2;
  }
  __syncthreads();
  const float inv = __fdividef(1.f, sred[0]);
  __syncthreads();

  float4 p = make_float4(0.f,0.f,0.f,0.f);
  const float4* lp = (const float4*)(lo + (size_t)b*512*1024) + tid;
  for (int t=0;t<512;t++){
    float a = sa[t];
    float4 v = lp[(size_t)t*256];
    p.x += a*v.x; p.y += a*v.y; p.z += a*v.z; p.w += a*v.w;
  }
  spool[tid*4+0] = p.x*inv; spool[tid*4+1] = p.y*inv;
  spool[tid*4+2] = p.z*inv; spool[tid*4+3] = p.w*inv;
  __syncthreads();

  float s = 0.f;
  #pragma unroll
  for (int i=0;i<32;i++) s += spool[lane + i*32]*__ldg(Wc + w*1024 + lane + i*32);
  #pragma unroll
  for (int o=16;o;o>>=1) s += __shfl_xor_sync(0xffffffffu, s, o);
  if (lane==0) out[b*8 + w] = s + bc[w];
}

// ------------------------- launch --------------------------------------------
extern "C" void kernel_launch(void* const* d_in, const int* in_sizes, int n_in,
                              void* d_out, int out_size) {
  const float* x    = (const float*)d_in[0];
  const int*   lens = (const int*)  d_in[1];
  const float* W1   = (const float*)d_in[2];
  const float* b1   = (const float*)d_in[3];
  const float* g1   = (const float*)d_in[4];
  const float* be1  = (const float*)d_in[5];
  const float* W2   = (const float*)d_in[6];
  const float* b2   = (const float*)d_in[7];
  const float* g2   = (const float*)d_in[8];
  const float* be2  = (const float*)d_in[9];
  const float* wih  = (const float*)d_in[10];
  const float* whh  = (const float*)d_in[11];
  const float* bih  = (const float*)d_in[12];
  const float* bhh  = (const float*)d_in[13];
  const float* w_u  = (const float*)d_in[14];
  const float* b_u  = (const float*)d_in[15];
  const float* Wc   = (const float*)d_in[16];
  const float* bc   = (const float*)d_in[17];
  float* out = (float*)d_out;

  cudaFuncSetAttribute(lstm_kernel, cudaFuncAttributeMaxDynamicSharedMemorySize,
                       LSTM_SMEM);

  float *p_h1, *p_h2, *p_xp, *p_lo1, *p_lo2;
  cudaGetSymbolAddress((void**)&p_h1,  g_h1);
  cudaGetSymbolAddress((void**)&p_h2,  g_h2);
  cudaGetSymbolAddress((void**)&p_xp,  g_xp);
  cudaGetSymbolAddress((void**)&p_lo1, g_lo1);
  cudaGetSymbolAddress((void**)&p_lo2, g_lo2);

  dim3 gmlp(128, 8);   // M/128 x 1024/128
  dim3 gxp (128, 32);  // M/128 x 4096/128

  gemm_tf32<<<gmlp, 256>>>(x, W1, b1, nullptr, p_h1, MT, 1024, 256);
  ln_lrelu<<<MT, 256>>>(p_h1, g1, be1, nullptr, 0);
  gemm_tf32<<<gmlp, 256>>>(p_h1, W2, b2, nullptr, p_h2, MT, 1024, 1024);
  ln_lrelu<<<MT, 256>>>(p_h2, g2, be2, lens, 1);

  // LSTM layer 1
  gemm_tf32<<<gxp, 256>>>(p_h2, wih, bih, bhh, p_xp, MT, 4096, 1024);
  lstm_kernel<<<128, 256, LSTM_SMEM>>>(p_xp, whh, p_lo1);
  // LSTM layer 2
  gemm_tf32<<<gxp, 256>>>(p_lo1, wih + (size_t)2*2048*1024, bih + 4096,
                          bhh + 4096, p_xp, MT, 4096, 1024);
  lstm_kernel<<<128, 256, LSTM_SMEM>>>(p_xp, whh + (size_t)2*2048*512, p_lo2);

  attn_kernel<<<32, 256>>>(p_lo2, w_u, b_u, Wc, bc, lens, out);
}

// round 5
// speedup vs baseline: 1.7782x; 1.7782x over previous
#include <cuda_runtime.h>
#include <cstdint>
#include <cstddef>

#define MT 16384            // B*T
#define GEMM_SMEM (2*2*4608*4)                 // 73728 B
#define LSTM_SMEM ((512*40 + 8*32*34)*4)       // 116736 B

// ------------------------- static device scratch -----------------------------
__device__ float g_h1 [(size_t)MT*1024];
__device__ float g_h2 [(size_t)MT*1024];
__device__ float g_xp [(size_t)MT*4096];
__device__ float g_lo1[(size_t)MT*1024];
__device__ float g_lo2[(size_t)MT*1024];
__device__ float g_xr [(size_t)MT*256];
__device__ float g_w1r[(size_t)1024*256];
__device__ float g_w2r[(size_t)1024*1024];
__device__ float g_wihr[(size_t)2*4096*1024];
__device__ float g_hbuf[2*2*512*32];     // [parity][dir][unit][batch]
__device__ unsigned g_barcnt[2];
__device__ unsigned g_bargen[2];

// ------------------------- helpers -------------------------------------------
__device__ __forceinline__ uint32_t f2tf(float x){
  uint32_t r; asm("cvt.rna.tf32.f32 %0, %1;" : "=r"(r) : "f"(x)); return r;
}
__device__ __forceinline__ float fsig(float x){
  return __fdividef(1.f, 1.f + __expf(-x));
}
__device__ __forceinline__ float ftanh(float x){
  return 1.f - __fdividef(2.f, __expf(2.f*x) + 1.f);
}
__device__ __forceinline__ void mma8(float c[4], const uint32_t a[4], const uint32_t b[2]){
  asm volatile("mma.sync.aligned.m16n8k8.row.col.f32.tf32.tf32.f32 "
    "{%0,%1,%2,%3}, {%4,%5,%6,%7}, {%8,%9}, {%0,%1,%2,%3};"
    : "+f"(c[0]), "+f"(c[1]), "+f"(c[2]), "+f"(c[3])
    : "r"(a[0]), "r"(a[1]), "r"(a[2]), "r"(a[3]), "r"(b[0]), "r"(b[1]));
}

// ------------------------- pre-round to tf32 ---------------------------------
__global__ __launch_bounds__(256) void round_k(const float4* __restrict__ s,
                                               float4* __restrict__ d, int n4){
  int i = blockIdx.x*256 + threadIdx.x;
  if (i < n4){
    float4 v = s[i];
    d[i] = make_float4(__uint_as_float(f2tf(v.x)), __uint_as_float(f2tf(v.y)),
                       __uint_as_float(f2tf(v.z)), __uint_as_float(f2tf(v.w)));
  }
}

// ---------------- TF32 GEMM: C[M,N] = A[M,K]*B[N,K]^T (+bias1 +bias2) --------
// Inputs already tf32-rounded. BM=BN=128, BK=32, cp.async double buffer.
__device__ __forceinline__ void gemm_issue(uint32_t sbase, int stage,
    const float* A, const float* B, int K, int m0, int n0, int k0, int tid){
  const float* Ap = A + (size_t)m0*K + k0;
  const float* Bp = B + (size_t)n0*K + k0;
  #pragma unroll
  for (int i=0;i<4;i++){
    int c = tid + i*256;
    int row = c>>3, kq = (c&7)<<2;
    uint32_t da = sbase + (uint32_t)(stage*4608 + row*36 + kq)*4u;
    uint32_t db = sbase + (uint32_t)(9216 + stage*4608 + row*36 + kq)*4u;
    asm volatile("cp.async.cg.shared.global [%0], [%1], 16;"
                 :: "r"(da), "l"(Ap + (size_t)row*K + kq));
    asm volatile("cp.async.cg.shared.global [%0], [%1], 16;"
                 :: "r"(db), "l"(Bp + (size_t)row*K + kq));
  }
  asm volatile("cp.async.commit_group;");
}

__global__ __launch_bounds__(256) void gemm_tf32(
    const float* __restrict__ A, const float* __restrict__ B,
    const float* __restrict__ bias1, const float* __restrict__ bias2,
    float* __restrict__ C, int M, int N, int K)
{
  extern __shared__ char dynsm[];
  uint32_t* sm32 = (uint32_t*)dynsm;
  const uint32_t sbase = (uint32_t)__cvta_generic_to_shared(dynsm);
  const int tid  = threadIdx.x;
  const int warp = tid >> 5, lane = tid & 31;
  const int gid  = lane >> 2, tig = lane & 3;
  const int wm   = warp & 1,  wn  = warp >> 1;
  const int m0 = blockIdx.x * 128, n0 = blockIdx.y * 128;
  const int NK = K >> 5;

  float acc[4][4][4];
  #pragma unroll
  for (int a=0;a<4;a++)
    #pragma unroll
    for (int b=0;b<4;b++)
      #pragma unroll
      for (int c=0;c<4;c++) acc[a][b][c] = 0.f;

  gemm_issue(sbase, 0, A, B, K, m0, n0, 0, tid);
  gemm_issue(sbase, 1, A, B, K, m0, n0, 32, tid);

  for (int i = 0; i < NK; ++i){
    asm volatile("cp.async.wait_group 1;");
    __syncthreads();
    const int s = i & 1;
    const uint32_t* Asb = sm32 + s*4608;
    const uint32_t* Bsb = sm32 + 9216 + s*4608;

    #pragma unroll
    for (int kt = 0; kt < 4; ++kt){
      uint32_t a[4][4], b[4][2];
      #pragma unroll
      for (int mt = 0; mt < 4; ++mt){
        const uint32_t* p = Asb + (wm*64 + mt*16 + gid)*36 + kt*8;
        a[mt][0] = p[tig];        a[mt][1] = p[8*36 + tig];
        a[mt][2] = p[tig+4];      a[mt][3] = p[8*36 + tig+4];
      }
      #pragma unroll
      for (int nt = 0; nt < 4; ++nt){
        const uint32_t* p = Bsb + (wn*32 + nt*8 + gid)*36 + kt*8;
        b[nt][0] = p[tig];        b[nt][1] = p[tig+4];
      }
      #pragma unroll
      for (int mt = 0; mt < 4; ++mt)
        #pragma unroll
        for (int nt = 0; nt < 4; ++nt)
          mma8(acc[mt][nt], a[mt], b[nt]);
    }
    __syncthreads();
    if (i + 2 < NK) gemm_issue(sbase, s, A, B, K, m0, n0, (i+2)*32, tid);
    else asm volatile("cp.async.commit_group;");
  }

  #pragma unroll
  for (int mt = 0; mt < 4; ++mt)
    #pragma unroll
    for (int nt = 0; nt < 4; ++nt){
      int row = m0 + wm*64 + mt*16 + gid;
      int col = n0 + wn*32 + nt*8 + tig*2;
      float ba = 0.f, bbv = 0.f;
      if (bias1){ ba += __ldg(bias1+col); bbv += __ldg(bias1+col+1); }
      if (bias2){ ba += __ldg(bias2+col); bbv += __ldg(bias2+col+1); }
      float2 v0 = make_float2(acc[mt][nt][0]+ba, acc[mt][nt][1]+bbv);
      float2 v1 = make_float2(acc[mt][nt][2]+ba, acc[mt][nt][3]+bbv);
      *(float2*)&C[(size_t)row*N + col]     = v0;
      *(float2*)&C[(size_t)(row+8)*N + col] = v1;
    }
}

// ---------------- LayerNorm + LeakyReLU (+ mask), tf32-rounded output --------
__global__ __launch_bounds__(256) void ln_lrelu(float* __restrict__ h,
    const float* __restrict__ g, const float* __restrict__ be,
    const int* __restrict__ lens, int use_mask)
{
  __shared__ float sred[8];
  const int row = blockIdx.x, tid = threadIdx.x, lane = tid & 31, w = tid >> 5;
  float* hp = h + (size_t)row*1024;
  float v[4]; float s = 0.f;
  #pragma unroll
  for (int i=0;i<4;i++){ v[i] = hp[tid + i*256]; s += v[i]; }
  #pragma unroll
  for (int o=16;o;o>>=1) s += __shfl_xor_sync(0xffffffffu, s, o);
  if (lane==0) sred[w] = s;
  __syncthreads();
  if (w==0){
    float t2 = (lane < 8) ? sred[lane] : 0.f;
    #pragma unroll
    for (int o=4;o;o>>=1) t2 += __shfl_xor_sync(0xffffffffu, t2, o);
    if (lane==0) sred[0] = t2;
  }
  __syncthreads();
  float mean = sred[0] * (1.f/1024.f);
  __syncthreads();
  float q = 0.f;
  #pragma unroll
  for (int i=0;i<4;i++){ float d = v[i]-mean; q += d*d; }
  #pragma unroll
  for (int o=16;o;o>>=1) q += __shfl_xor_sync(0xffffffffu, q, o);
  if (lane==0) sred[w] = q;
  __syncthreads();
  if (w==0){
    float t2 = (lane < 8) ? sred[lane] : 0.f;
    #pragma unroll
    for (int o=4;o;o>>=1) t2 += __shfl_xor_sync(0xffffffffu, t2, o);
    if (lane==0) sred[0] = t2;
  }
  __syncthreads();
  float rstd = rsqrtf(sred[0]*(1.f/1024.f) + 1e-5f);
  float msk = 1.f;
  if (use_mask){ int b = row >> 9, t = row & 511; msk = (t < lens[b]) ? 1.f : 0.f; }
  #pragma unroll
  for (int i=0;i<4;i++){
    int j = tid + i*256;
    float y = (v[i]-mean)*rstd*g[j] + be[j];
    y = (y >= 0.f) ? y : 0.01f*y;
    hp[j] = __uint_as_float(f2tf(y * msk));
  }
}

// ---------------- persistent bidirectional LSTM layer (tensor-core) ----------
// 128 blocks x 256 threads. dir = blk>>6; 8 units (32 gate rows) per block.
// Recurrent W held as mma A-fragments in registers; h in smem [k][40] tf32.
__global__ __launch_bounds__(256) void lstm_kernel(
    const float* __restrict__ xp,     // [16384][4096]: dir0 2048 | dir1 2048
    const float* __restrict__ whh_l,  // [2][2048][512] for this layer
    float* __restrict__ lo)           // [16384][1024]: fwd 512 | bwd 512
{
  extern __shared__ char dynsm[];
  float* hs   = (float*)dynsm;              // [512][40]
  float* part = (float*)dynsm + 20480;      // [8][32][34]
  const int tid = threadIdx.x;
  const int dir = blockIdx.x >> 6;
  const int u0  = (blockIdx.x & 63) * 8;
  const int w   = tid >> 5, lane = tid & 31;
  const int gid = lane >> 2, tig = lane & 3;

  // A fragments: local row r -> global row (r>>3)*512 + u0 + (r&7)
  uint32_t afr[2][8][4];
  {
    const float* base = whh_l + (size_t)dir*2048*512;
    #pragma unroll
    for (int mt = 0; mt < 2; ++mt)
      #pragma unroll
      for (int kt = 0; kt < 8; ++kt){
        int r0 = mt*16 + gid, r1 = r0 + 8;
        int k0 = w*64 + kt*8 + tig;
        int g0 = (r0>>3)*512 + u0 + (r0&7);
        int g1 = (r1>>3)*512 + u0 + (r1&7);
        afr[mt][kt][0] = f2tf(base[(size_t)g0*512 + k0]);
        afr[mt][kt][1] = f2tf(base[(size_t)g1*512 + k0]);
        afr[mt][kt][2] = f2tf(base[(size_t)g0*512 + k0+4]);
        afr[mt][kt][3] = f2tf(base[(size_t)g1*512 + k0+4]);
      }
  }

  const int ub = tid & 7, bb = tid >> 3;
  float c_reg = 0.f;

  for (int i = tid; i < 20480; i += 256) hs[i] = 0.f;
  __syncthreads();

  volatile unsigned* vgen = (volatile unsigned*)&g_bargen[dir];

  for (int t = 0; t < 512; ++t){
    const int te = dir ? (511 - t) : t;

    const float* xpp = xp + ((size_t)(bb*512 + te))*4096 + dir*2048 + u0 + ub;
    float xv0 = __ldcs(xpp);
    float xv1 = __ldcs(xpp + 512);
    float xv2 = __ldcs(xpp + 1024);
    float xv3 = __ldcs(xpp + 1536);

    // ---- tensor-core partial: C[32x32] over K-chunk [w*64, w*64+64) -------
    float acc[2][4][4];
    #pragma unroll
    for (int a=0;a<2;a++)
      #pragma unroll
      for (int b=0;b<4;b++)
        #pragma unroll
        for (int c=0;c<4;c++) acc[a][b][c] = 0.f;

    #pragma unroll
    for (int kt = 0; kt < 8; ++kt){
      const int krow = w*64 + kt*8 + tig;
      uint32_t b[4][2];
      #pragma unroll
      for (int nt = 0; nt < 4; ++nt){
        b[nt][0] = __float_as_uint(hs[(size_t)krow*40     + nt*8 + gid]);
        b[nt][1] = __float_as_uint(hs[(size_t)(krow+4)*40 + nt*8 + gid]);
      }
      #pragma unroll
      for (int mt = 0; mt < 2; ++mt)
        #pragma unroll
        for (int nt = 0; nt < 4; ++nt)
          mma8(acc[mt][nt], afr[mt][kt], b[nt]);
    }
    {
      float* pp = part + w*1088;   // 32*34
      #pragma unroll
      for (int mt = 0; mt < 2; ++mt)
        #pragma unroll
        for (int nt = 0; nt < 4; ++nt){
          int row = mt*16 + gid, col = nt*8 + tig*2;
          *(float2*)&pp[row*34 + col]     = make_float2(acc[mt][nt][0], acc[mt][nt][1]);
          *(float2*)&pp[(row+8)*34 + col] = make_float2(acc[mt][nt][2], acc[mt][nt][3]);
        }
    }
    __syncthreads();

    // ---- reduce 8 K-chunks + cell update (thread = (bb, ub)) --------------
    float gsum[4];
    #pragma unroll
    for (int g4 = 0; g4 < 4; ++g4){
      int row = g4*8 + ub;
      float s = 0.f;
      #pragma unroll
      for (int ww = 0; ww < 8; ++ww) s += part[ww*1088 + row*34 + bb];
      gsum[g4] = s;
    }
    float ig = fsig (gsum[0] + xv0);
    float fg = fsig (gsum[1] + xv1);
    float gt = ftanh(gsum[2] + xv2);
    float og = fsig (gsum[3] + xv3);
    c_reg = fg*c_reg + ig*gt;
    float hv = og * ftanh(c_reg);
    float hr = __uint_as_float(f2tf(hv));

    lo[((size_t)(bb*512 + te))*1024 + dir*512 + u0 + ub] = hr;
    __stcg(g_hbuf + ((t & 1)*2 + dir)*16384 + (u0 + ub)*32 + bb, hr);

    // ---- per-dir grid barrier ---------------------------------------------
    __threadfence();
    __syncthreads();
    if (tid == 0){
      unsigned gen = *vgen;
      unsigned a = atomicAdd(&g_barcnt[dir], 1u);
      if (a == 63u){
        atomicExch(&g_barcnt[dir], 0u);
        __threadfence();
        atomicAdd(&g_bargen[dir], 1u);
      } else {
        while (*vgen == gen) { }
        __threadfence();
      }
    }
    __syncthreads();

    // ---- reload full h(t) into padded smem --------------------------------
    {
      const float4* src = (const float4*)(g_hbuf + ((t&1)*2 + dir)*16384);
      #pragma unroll
      for (int j = 0; j < 16; ++j){
        int idx = tid + j*256;            // float4 index, 0..4095
        int k = idx >> 3, bq = idx & 7;
        *(float4*)&hs[(size_t)k*40 + bq*4] = __ldcg(src + idx);
      }
    }
    __syncthreads();
  }
}

// ---------------- attention pooling + classifier head ------------------------
__global__ __launch_bounds__(256) void attn_kernel(
    const float* __restrict__ lo, const float* __restrict__ w_u,
    const float* __restrict__ b_u, const float* __restrict__ Wc,
    const float* __restrict__ bc, const int* __restrict__ lens,
    float* __restrict__ out)
{
  __shared__ float sw[1024];
  __shared__ float sa[512];
  __shared__ float sred[8];
  __shared__ float spool[1024];
  const int b = blockIdx.x, tid = threadIdx.x, lane = tid & 31, w = tid >> 5;
  const int len = lens[b];
  for (int i=tid;i<1024;i+=256) sw[i] = w_u[i];
  __syncthreads();

  for (int t = w; t < 512; t += 8){
    float s = 0.f;
    const float* hp = lo + ((size_t)(b*512+t))*1024;
    #pragma unroll
    for (int i=0;i<32;i++) s += hp[lane + i*32]*sw[lane + i*32];
    #pragma unroll
    for (int o=16;o;o>>=1) s += __shfl_xor_sync(0xffffffffu, s, o);
    if (lane==0) sa[t] = (t < len) ? (s + b_u[0]) : -INFINITY;
  }
  __syncthreads();

  float m = -INFINITY;
  for (int i=tid;i<512;i+=256) m = fmaxf(m, sa[i]);
  #pragma unroll
  for (int o=16;o;o>>=1) m = fmaxf(m, __shfl_xor_sync(0xffffffffu, m, o));
  if (lane==0) sred[w] = m;
  __syncthreads();
  if (w==0){
    float t2 = (lane<8)?sred[lane]:-INFINITY;
    #pragma unroll
    for (int o=4;o;o>>=1) t2 = fmaxf(t2, __shfl_xor_sync(0xffffffffu, t2, o));
    if (lane==0) sred[0] = t2;
  }
  __syncthreads();
  m = sred[0];
  __syncthreads();

  float ssum = 0.f;
  for (int i=tid;i<512;i+=256){ float e = __expf(sa[i]-m); sa[i]=e; ssum += e; }
  #pragma unroll
  for (int o=16;o;o>>=1) ssum += __shfl_xor_sync(0xffffffffu, ssum, o);
  if (lane==0) sred[w] = ssum;
  __syncthreads();
  if (w==0){
    float t2 = (lane<8)?sred[lane]:0.f;
    #pragma unroll
    for (int o=4;o;o>>=1) t2 += __shfl_xor_sync(0xffffffffu, t2, o);
    if (lane==0) sred[0] = t2;
  }
  __syncthreads();
  const float inv = __fdividef(1.f, sred[0]);
  __syncthreads();

  float4 p = make_float4(0.f,0.f,0.f,0.f);
  const float4* lp = (const float4*)(lo + (size_t)b*512*1024) + tid;
  for (int t=0;t<512;t++){
    float a = sa[t];
    float4 v = lp[(size_t)t*256];
    p.x += a*v.x; p.y += a*v.y; p.z += a*v.z; p.w += a*v.w;
  }
  spool[tid*4+0] = p.x*inv; spool[tid*4+1] = p.y*inv;
  spool[tid*4+2] = p.z*inv; spool[tid*4+3] = p.w*inv;
  __syncthreads();

  float s = 0.f;
  #pragma unroll
  for (int i=0;i<32;i++) s += spool[lane + i*32]*__ldg(Wc + w*1024 + lane + i*32);
  #pragma unroll
  for (int o=16;o;o>>=1) s += __shfl_xor_sync(0xffffffffu, s, o);
  if (lane==0) out[b*8 + w] = s + bc[w];
}

// ------------------------- launch --------------------------------------------
extern "C" void kernel_launch(void* const* d_in, const int* in_sizes, int n_in,
                              void* d_out, int out_size) {
  const float* x    = (const float*)d_in[0];
  const int*   lens = (const int*)  d_in[1];
  const float* W1   = (const float*)d_in[2];
  const float* b1   = (const float*)d_in[3];
  const float* g1   = (const float*)d_in[4];
  const float* be1  = (const float*)d_in[5];
  const float* W2   = (const float*)d_in[6];
  const float* b2   = (const float*)d_in[7];
  const float* g2   = (const float*)d_in[8];
  const float* be2  = (const float*)d_in[9];
  const float* wih  = (const float*)d_in[10];
  const float* whh  = (const float*)d_in[11];
  const float* bih  = (const float*)d_in[12];
  const float* bhh  = (const float*)d_in[13];
  const float* w_u  = (const float*)d_in[14];
  const float* b_u  = (const float*)d_in[15];
  const float* Wc   = (const float*)d_in[16];
  const float* bc   = (const float*)d_in[17];
  float* out = (float*)d_out;

  cudaFuncSetAttribute(gemm_tf32, cudaFuncAttributeMaxDynamicSharedMemorySize,
                       GEMM_SMEM);
  cudaFuncSetAttribute(lstm_kernel, cudaFuncAttributeMaxDynamicSharedMemorySize,
                       LSTM_SMEM);

  float *p_h1, *p_h2, *p_xp, *p_lo1, *p_lo2, *p_xr, *p_w1r, *p_w2r, *p_wihr;
  cudaGetSymbolAddress((void**)&p_h1,  g_h1);
  cudaGetSymbolAddress((void**)&p_h2,  g_h2);
  cudaGetSymbolAddress((void**)&p_xp,  g_xp);
  cudaGetSymbolAddress((void**)&p_lo1, g_lo1);
  cudaGetSymbolAddress((void**)&p_lo2, g_lo2);
  cudaGetSymbolAddress((void**)&p_xr,  g_xr);
  cudaGetSymbolAddress((void**)&p_w1r, g_w1r);
  cudaGetSymbolAddress((void**)&p_w2r, g_w2r);
  cudaGetSymbolAddress((void**)&p_wihr,g_wihr);

  // pre-round all GEMM operands to tf32 (values become exact tf32)
  round_k<<<4096, 256>>>((const float4*)x,   (float4*)p_xr,  4194304/4);
  round_k<<< 256, 256>>>((const float4*)W1,  (float4*)p_w1r,  262144/4);
  round_k<<<1024, 256>>>((const float4*)W2,  (float4*)p_w2r, 1048576/4);
  round_k<<<4096, 256>>>((const float4*)wih, (float4*)p_wihr, 4194304/4);
  round_k<<<4096, 256>>>((const float4*)(wih + (size_t)4194304),
                         (float4*)(p_wihr + (size_t)4194304), 4194304/4);

  dim3 gmlp(128, 8);   // M/128 x 1024/128
  dim3 gxp (128, 32);  // M/128 x 4096/128

  gemm_tf32<<<gmlp, 256, GEMM_SMEM>>>(p_xr, p_w1r, b1, nullptr, p_h1, MT, 1024, 256);
  ln_lrelu<<<MT, 256>>>(p_h1, g1, be1, nullptr, 0);
  gemm_tf32<<<gmlp, 256, GEMM_SMEM>>>(p_h1, p_w2r, b2, nullptr, p_h2, MT, 1024, 1024);
  ln_lrelu<<<MT, 256>>>(p_h2, g2, be2, lens, 1);

  // LSTM layer 1
  gemm_tf32<<<gxp, 256, GEMM_SMEM>>>(p_h2, p_wihr, bih, bhh, p_xp, MT, 4096, 1024);
  lstm_kernel<<<128, 256, LSTM_SMEM>>>(p_xp, whh, p_lo1);
  // LSTM layer 2
  gemm_tf32<<<gxp, 256, GEMM_SMEM>>>(p_lo1, p_wihr + (size_t)4194304, bih + 4096,
                                     bhh + 4096, p_xp, MT, 4096, 1024);
  lstm_kernel<<<128, 256, LSTM_SMEM>>>(p_xp, whh + (size_t)2*2048*512, p_lo2);

  attn_kernel<<<32, 256>>>(p_lo2, w_u, b_u, Wc, bc, lens, out);
}